// round 2
// baseline (speedup 1.0000x reference)
#include <cuda_runtime.h>
#include <math.h>

// VanillaVQ: z_e (8,64,64,64) fp32, embedding (8192,64) fp32.
// Outputs (concat fp32): z_q (2097152) | indices (32768) | commit_loss | perplexity | usage.

#define K_CODES 8192
#define D_DIM   64
#define N_ROWS  32768      // 8*64*64
#define HW      4096       // 64*64
#define TK      128        // codes per smem tile
#define THREADS 128
#define BETA    0.25f

#define NZ (N_ROWS * D_DIM)
#define NI N_ROWS

// Scratch (no cudaMalloc allowed)
__device__ float g_b2[K_CODES];      // |e_k|^2, XLA warp-tree order
__device__ int   g_counts[K_CODES];
__device__ float g_loss;

// ---------------------------------------------------------------------------
// Kernel 1: per-code squared norm, replicating XLA GPU row-reduction order:
// p_d = fl(e_d*e_d); lane partial = fl(p_lane + p_{lane+32}); shfl-down tree
// with offsets 16,8,4,2,1. One warp per code.
// ---------------------------------------------------------------------------
__global__ void vq_prep(const float* __restrict__ emb) {
    int gtid = blockIdx.x * blockDim.x + threadIdx.x;
    int k    = gtid >> 5;
    int lane = gtid & 31;
    if (k < K_CODES) {
        const float* e = emb + (size_t)k * D_DIM;
        float p1 = __fmul_rn(e[lane],      e[lane]);
        float p2 = __fmul_rn(e[lane + 32], e[lane + 32]);
        float t  = __fadd_rn(p1, p2);
#pragma unroll
        for (int off = 16; off >= 1; off >>= 1)
            t = __fadd_rn(t, __shfl_down_sync(0xFFFFFFFFu, t, off));
        if (lane == 0) {
            g_b2[k] = t;
            g_counts[k] = 0;
        }
    }
    if (gtid == 0) g_loss = 0.0f;
}

// ---------------------------------------------------------------------------
// Kernel 2: fused distance + argmin + gather + STE z_q + loss partial.
// Score replicates the reference exactly:
//   dist_k = fl( fl(a2 - 2*dot_k) + b2_k )
// with a2 in XLA warp-tree order (emulated in-registers) and dot_k a
// sequential FMA chain d=0..63 (cuBLAS SGEMM order). Strict < keeps the
// first minimum (jnp.argmin tie-break).
// ---------------------------------------------------------------------------
__global__ __launch_bounds__(THREADS)
void vq_main(const float* __restrict__ z, const float* __restrict__ emb,
             float* __restrict__ out, int out_size) {
    __shared__ float se[TK][D_DIM];   // 32 KB code tile
    __shared__ float sb2[TK];

    const int row = blockIdx.x * THREADS + threadIdx.x;
    const int b  = row >> 12;
    const int hw = row & 4095;

    // z_e[b, d, h, w]: stride HW between d's; coalesced across warp
    const float* zbase = z + (size_t)b * (D_DIM * HW) + hw;
    float zr[D_DIM];
#pragma unroll
    for (int d = 0; d < D_DIM; d++) zr[d] = zbase[(size_t)d * HW];

    // a2 = |z|^2 in XLA warp-tree order (emulated with a local array)
    float a2;
    {
        float t[32];
#pragma unroll
        for (int l = 0; l < 32; l++)
            t[l] = __fadd_rn(__fmul_rn(zr[l], zr[l]),
                             __fmul_rn(zr[l + 32], zr[l + 32]));
#pragma unroll
        for (int off = 16; off >= 1; off >>= 1)
#pragma unroll
            for (int l = 0; l < 16; l++)
                if (l < off) t[l] = __fadd_rn(t[l], t[l + off]);
        a2 = t[0];
    }

    float best = 3.4e38f;
    int   bidx = 0;

    for (int k0 = 0; k0 < K_CODES; k0 += TK) {
        __syncthreads();
        const float4* gsrc = reinterpret_cast<const float4*>(emb + (size_t)k0 * D_DIM);
        float4* sdst = reinterpret_cast<float4*>(&se[0][0]);
#pragma unroll
        for (int i = threadIdx.x; i < TK * (D_DIM / 4); i += THREADS) sdst[i] = gsrc[i];
        if (threadIdx.x < TK) sb2[threadIdx.x] = g_b2[k0 + threadIdx.x];
        __syncthreads();

#pragma unroll 1
        for (int kk = 0; kk < TK; kk += 4) {
            float a0 = 0.0f, a1 = 0.0f, a2c = 0.0f, a3 = 0.0f;
            const float4* e0 = reinterpret_cast<const float4*>(se[kk + 0]);
            const float4* e1 = reinterpret_cast<const float4*>(se[kk + 1]);
            const float4* e2 = reinterpret_cast<const float4*>(se[kk + 2]);
            const float4* e3 = reinterpret_cast<const float4*>(se[kk + 3]);
#pragma unroll
            for (int i = 0; i < D_DIM / 4; i++) {
                float4 v0 = e0[i], v1 = e1[i], v2 = e2[i], v3 = e3[i];
                float zx = zr[4 * i + 0], zy = zr[4 * i + 1];
                float zz = zr[4 * i + 2], zw = zr[4 * i + 3];
                a0 = fmaf(zx, v0.x, a0); a0 = fmaf(zy, v0.y, a0);
                a0 = fmaf(zz, v0.z, a0); a0 = fmaf(zw, v0.w, a0);
                a1 = fmaf(zx, v1.x, a1); a1 = fmaf(zy, v1.y, a1);
                a1 = fmaf(zz, v1.z, a1); a1 = fmaf(zw, v1.w, a1);
                a2c = fmaf(zx, v2.x, a2c); a2c = fmaf(zy, v2.y, a2c);
                a2c = fmaf(zz, v2.z, a2c); a2c = fmaf(zw, v2.w, a2c);
                a3 = fmaf(zx, v3.x, a3); a3 = fmaf(zy, v3.y, a3);
                a3 = fmaf(zz, v3.z, a3); a3 = fmaf(zw, v3.w, a3);
            }
            // dist = (a2 - 2*dot) + b2, rounded exactly like the reference
            float d0 = __fadd_rn(__fsub_rn(a2, __fmul_rn(2.0f, a0)),  sb2[kk + 0]);
            float d1 = __fadd_rn(__fsub_rn(a2, __fmul_rn(2.0f, a1)),  sb2[kk + 1]);
            float d2 = __fadd_rn(__fsub_rn(a2, __fmul_rn(2.0f, a2c)), sb2[kk + 2]);
            float d3 = __fadd_rn(__fsub_rn(a2, __fmul_rn(2.0f, a3)),  sb2[kk + 3]);
            if (d0 < best) { best = d0; bidx = k0 + kk + 0; }
            if (d1 < best) { best = d1; bidx = k0 + kk + 1; }
            if (d2 < best) { best = d2; bidx = k0 + kk + 2; }
            if (d3 < best) { best = d3; bidx = k0 + kk + 3; }
        }
    }

    // gather chosen code; z_q = z + (q - z) (STE, bitwise like reference)
    const float* eb = emb + (size_t)bidx * D_DIM;
    float ssq = 0.0f;
    float* zqbase = out + (size_t)b * (D_DIM * HW) + hw;
    bool write_zq = (out_size >= NZ);
#pragma unroll
    for (int d = 0; d < D_DIM; d++) {
        float ev = eb[d];
        float df = __fsub_rn(zr[d], ev);           // z - q
        ssq = fmaf(df, df, ssq);
        if (write_zq)
            zqbase[(size_t)d * HW] = __fadd_rn(zr[d], __fsub_rn(ev, zr[d]));
    }

    if (out_size >= NZ + NI) out[NZ + row] = (float)bidx;

    atomicAdd(&g_counts[bidx], 1);

#pragma unroll
    for (int o = 16; o > 0; o >>= 1) ssq += __shfl_down_sync(0xFFFFFFFFu, ssq, o);
    if ((threadIdx.x & 31) == 0) atomicAdd(&g_loss, ssq);
}

// ---------------------------------------------------------------------------
// Kernel 3: scalars (commit_loss, perplexity, usage)
// ---------------------------------------------------------------------------
__global__ void vq_finalize(float* __restrict__ out, int out_size) {
    __shared__ float sH[256];
    __shared__ int   sU[256];
    const int tid = threadIdx.x;
    float H = 0.0f;
    int used = 0;
    for (int k = tid; k < K_CODES; k += 256) {
        float c = (float)g_counts[k];
        if (c > 0.0f) used++;
        float avg = c * (1.0f / (float)N_ROWS);
        H = fmaf(avg, logf(avg + 1e-10f), H);
    }
    sH[tid] = H;
    sU[tid] = used;
    __syncthreads();
    for (int s = 128; s > 0; s >>= 1) {
        if (tid < s) { sH[tid] += sH[tid + s]; sU[tid] += sU[tid + s]; }
        __syncthreads();
    }
    if (tid == 0 && out_size >= NZ + NI + 3) {
        out[NZ + NI + 0] = BETA * g_loss / (float)(N_ROWS * D_DIM);
        out[NZ + NI + 1] = expf(-sH[0]);
        out[NZ + NI + 2] = (float)sU[0] / (float)K_CODES;
    }
}

// ---------------------------------------------------------------------------
extern "C" void kernel_launch(void* const* d_in, const int* in_sizes, int n_in,
                              void* d_out, int out_size) {
    const float* z   = (const float*)d_in[0];
    const float* emb = (const float*)d_in[1];
    float* out = (float*)d_out;

    vq_prep<<<(K_CODES * 32) / 256, 256>>>(emb);
    vq_main<<<N_ROWS / THREADS, THREADS>>>(z, emb, out, out_size);
    vq_finalize<<<1, 256>>>(out, out_size);
}

// round 3
// speedup vs baseline: 1.1889x; 1.1889x over previous
#include <cuda_runtime.h>
#include <math.h>

// VanillaVQ: z_e (8,64,64,64) fp32, embedding (8192,64) fp32.
// Outputs (concat fp32): z_q (2097152) | indices (32768) | commit_loss | perplexity | usage.

#define K_CODES 8192
#define D_DIM   64
#define N_ROWS  32768      // 8*64*64
#define HW      4096       // 64*64
#define TK      128        // codes per smem tile
#define THREADS 128
#define RPT     2          // rows per thread
#define BETA    0.25f

#define NZ (N_ROWS * D_DIM)
#define NI N_ROWS

typedef unsigned long long ull;

// Scratch (no cudaMalloc allowed)
__device__ float g_b2[K_CODES];      // |e_k|^2, XLA warp-tree order
__device__ int   g_counts[K_CODES];
__device__ float g_loss;

// packed helpers — each lane is an independent IEEE fp32 op (bitwise == scalar)
__device__ __forceinline__ ull pack2(float lo, float hi) {
    ull r; asm("mov.b64 %0, {%1,%2};" : "=l"(r) : "f"(lo), "f"(hi)); return r;
}
__device__ __forceinline__ void unpack2(float& lo, float& hi, ull v) {
    asm("mov.b64 {%0,%1}, %2;" : "=f"(lo), "=f"(hi) : "l"(v));
}
#define FMA2(acc, a, b) asm("fma.rn.f32x2 %0, %1, %2, %0;" : "+l"(acc) : "l"(a), "l"(b))
__device__ __forceinline__ ull fma2v(ull a, ull b, ull c) {
    ull r; asm("fma.rn.f32x2 %0, %1, %2, %3;" : "=l"(r) : "l"(a), "l"(b), "l"(c)); return r;
}
__device__ __forceinline__ ull add2v(ull a, ull b) {
    ull r; asm("add.rn.f32x2 %0, %1, %2;" : "=l"(r) : "l"(a), "l"(b)); return r;
}

// ---------------------------------------------------------------------------
// Kernel 1: per-code squared norm in XLA warp-tree order (one warp per code)
// ---------------------------------------------------------------------------
__global__ void vq_prep(const float* __restrict__ emb) {
    int gtid = blockIdx.x * blockDim.x + threadIdx.x;
    int k    = gtid >> 5;
    int lane = gtid & 31;
    if (k < K_CODES) {
        const float* e = emb + (size_t)k * D_DIM;
        float p1 = __fmul_rn(e[lane],      e[lane]);
        float p2 = __fmul_rn(e[lane + 32], e[lane + 32]);
        float t  = __fadd_rn(p1, p2);
#pragma unroll
        for (int off = 16; off >= 1; off >>= 1)
            t = __fadd_rn(t, __shfl_down_sync(0xFFFFFFFFu, t, off));
        if (lane == 0) {
            g_b2[k] = t;
            g_counts[k] = 0;
        }
    }
    if (gtid == 0) g_loss = 0.0f;
}

// ---------------------------------------------------------------------------
// Kernel 2: fused distance + argmin, packed f32x2, 2 rows/thread.
// Score bitwise-identical to reference: dist = fl(fl(a2 - 2*dot) + b2),
// dot = sequential fma chain d=0..63, a2 = XLA warp-tree order.
// ---------------------------------------------------------------------------
__global__ __launch_bounds__(THREADS, 1)
void vq_main(const float* __restrict__ z, const float* __restrict__ emb,
             float* __restrict__ out, int out_size) {
    __shared__ float se_t[D_DIM][TK];   // transposed tile: [dim][code], 32 KB
    __shared__ float sb2[TK];

    const int tid  = threadIdx.x;
    const int row0 = blockIdx.x * THREADS + tid;          // rows [0, 16384)
    const int row1 = row0 + N_ROWS / 2;                   // rows [16384, 32768)

    // load both z rows (coalesced: hw varies across threads)
    float zr0[D_DIM], zr1[D_DIM];
    {
        const int b0 = row0 >> 12, hw0 = row0 & 4095;
        const int b1 = row1 >> 12, hw1 = row1 & 4095;
        const float* zb0 = z + (size_t)b0 * (D_DIM * HW) + hw0;
        const float* zb1 = z + (size_t)b1 * (D_DIM * HW) + hw1;
#pragma unroll
        for (int d = 0; d < D_DIM; d++) { zr0[d] = zb0[(size_t)d * HW]; zr1[d] = zb1[(size_t)d * HW]; }
    }

    // a2 per row, XLA warp-tree order (in-register emulation)
    float a2_0, a2_1;
    {
        float t0[32], t1[32];
#pragma unroll
        for (int l = 0; l < 32; l++) {
            t0[l] = __fadd_rn(__fmul_rn(zr0[l], zr0[l]), __fmul_rn(zr0[l + 32], zr0[l + 32]));
            t1[l] = __fadd_rn(__fmul_rn(zr1[l], zr1[l]), __fmul_rn(zr1[l + 32], zr1[l + 32]));
        }
#pragma unroll
        for (int off = 16; off >= 1; off >>= 1)
#pragma unroll
            for (int l = 0; l < 16; l++)
                if (l < off) {
                    t0[l] = __fadd_rn(t0[l], t0[l + off]);
                    t1[l] = __fadd_rn(t1[l], t1[l + off]);
                }
        a2_0 = t0[0]; a2_1 = t1[0];
    }
    const ull a2p0 = pack2(a2_0, a2_0);
    const ull a2p1 = pack2(a2_1, a2_1);
    const ull NEG2 = pack2(-2.0f, -2.0f);

    float best0 = 3.4e38f, best1 = 3.4e38f;
    int   bidx0 = 0,       bidx1 = 0;

    for (int k0 = 0; k0 < K_CODES; k0 += TK) {
        __syncthreads();
        // tile load: thread owns code column (k0+tid); STS conflict-free per d-row
        {
            const float4* g = reinterpret_cast<const float4*>(emb + (size_t)(k0 + tid) * D_DIM);
#pragma unroll
            for (int j = 0; j < D_DIM / 4; j++) {
                float4 v = g[j];
                se_t[4 * j + 0][tid] = v.x;
                se_t[4 * j + 1][tid] = v.y;
                se_t[4 * j + 2][tid] = v.z;
                se_t[4 * j + 3][tid] = v.w;
            }
            sb2[tid] = g_b2[k0 + tid];
        }
        __syncthreads();

#pragma unroll 1
        for (int kk = 0; kk < TK; kk += 16) {
            ull acc0[8], acc1[8];
#pragma unroll
            for (int p = 0; p < 8; p++) { acc0[p] = 0ULL; acc1[p] = 0ULL; }

#pragma unroll 8
            for (int d = 0; d < D_DIM; d++) {
                const ull zp0 = pack2(zr0[d], zr0[d]);
                const ull zp1 = pack2(zr1[d], zr1[d]);
                const ulonglong2* ep = reinterpret_cast<const ulonglong2*>(&se_t[d][kk]);
#pragma unroll
                for (int g = 0; g < 4; g++) {
                    ulonglong2 e = ep[g];          // codes kk+4g .. kk+4g+3 at dim d
                    FMA2(acc0[2 * g + 0], zp0, e.x);
                    FMA2(acc0[2 * g + 1], zp0, e.y);
                    FMA2(acc1[2 * g + 0], zp1, e.x);
                    FMA2(acc1[2 * g + 1], zp1, e.y);
                }
            }

            // dist = fl(fl(a2 - 2*dot) + b2): fma(-2,dot,a2) is exact-equal to
            // sub(a2, 2*dot) since 2*dot is exact.
            const ull* b2p = reinterpret_cast<const ull*>(&sb2[kk]);
#pragma unroll
            for (int p = 0; p < 8; p++) {
                ull bb = b2p[p];
                ull d0p = add2v(fma2v(acc0[p], NEG2, a2p0), bb);
                ull d1p = add2v(fma2v(acc1[p], NEG2, a2p1), bb);
                float dl, dh;
                unpack2(dl, dh, d0p);
                if (dl < best0) { best0 = dl; bidx0 = k0 + kk + 2 * p + 0; }
                if (dh < best0) { best0 = dh; bidx0 = k0 + kk + 2 * p + 1; }
                unpack2(dl, dh, d1p);
                if (dl < best1) { best1 = dl; bidx1 = k0 + kk + 2 * p + 0; }
                if (dh < best1) { best1 = dh; bidx1 = k0 + kk + 2 * p + 1; }
            }
        }
    }

    // gather + STE z_q + loss partials for both rows
    float ssq = 0.0f;
    const bool write_zq = (out_size >= NZ);
    {
        const int b0 = row0 >> 12, hw0 = row0 & 4095;
        const float* eb = emb + (size_t)bidx0 * D_DIM;
        float* zqb = out + (size_t)b0 * (D_DIM * HW) + hw0;
#pragma unroll
        for (int d = 0; d < D_DIM; d++) {
            float ev = eb[d];
            float df = __fsub_rn(zr0[d], ev);
            ssq = fmaf(df, df, ssq);
            if (write_zq) zqb[(size_t)d * HW] = __fadd_rn(zr0[d], __fsub_rn(ev, zr0[d]));
        }
    }
    {
        const int b1 = row1 >> 12, hw1 = row1 & 4095;
        const float* eb = emb + (size_t)bidx1 * D_DIM;
        float* zqb = out + (size_t)b1 * (D_DIM * HW) + hw1;
#pragma unroll
        for (int d = 0; d < D_DIM; d++) {
            float ev = eb[d];
            float df = __fsub_rn(zr1[d], ev);
            ssq = fmaf(df, df, ssq);
            if (write_zq) zqb[(size_t)d * HW] = __fadd_rn(zr1[d], __fsub_rn(ev, zr1[d]));
        }
    }

    if (out_size >= NZ + NI) {
        out[NZ + row0] = (float)bidx0;
        out[NZ + row1] = (float)bidx1;
    }
    atomicAdd(&g_counts[bidx0], 1);
    atomicAdd(&g_counts[bidx1], 1);

#pragma unroll
    for (int o = 16; o > 0; o >>= 1) ssq += __shfl_down_sync(0xFFFFFFFFu, ssq, o);
    if ((tid & 31) == 0) atomicAdd(&g_loss, ssq);
}

// ---------------------------------------------------------------------------
// Kernel 3: scalars (commit_loss, perplexity, usage)
// ---------------------------------------------------------------------------
__global__ void vq_finalize(float* __restrict__ out, int out_size) {
    __shared__ float sH[256];
    __shared__ int   sU[256];
    const int tid = threadIdx.x;
    float H = 0.0f;
    int used = 0;
    for (int k = tid; k < K_CODES; k += 256) {
        float c = (float)g_counts[k];
        if (c > 0.0f) used++;
        float avg = c * (1.0f / (float)N_ROWS);
        H = fmaf(avg, logf(avg + 1e-10f), H);
    }
    sH[tid] = H;
    sU[tid] = used;
    __syncthreads();
    for (int s = 128; s > 0; s >>= 1) {
        if (tid < s) { sH[tid] += sH[tid + s]; sU[tid] += sU[tid + s]; }
        __syncthreads();
    }
    if (tid == 0 && out_size >= NZ + NI + 3) {
        out[NZ + NI + 0] = BETA * g_loss / (float)(N_ROWS * D_DIM);
        out[NZ + NI + 1] = expf(-sH[0]);
        out[NZ + NI + 2] = (float)sU[0] / (float)K_CODES;
    }
}

// ---------------------------------------------------------------------------
extern "C" void kernel_launch(void* const* d_in, const int* in_sizes, int n_in,
                              void* d_out, int out_size) {
    const float* z   = (const float*)d_in[0];
    const float* emb = (const float*)d_in[1];
    float* out = (float*)d_out;

    vq_prep<<<(K_CODES * 32) / 256, 256>>>(emb);
    vq_main<<<N_ROWS / (THREADS * RPT), THREADS>>>(z, emb, out, out_size);
    vq_finalize<<<1, 256>>>(out, out_size);
}